// round 1
// baseline (speedup 1.0000x reference)
#include <cuda_runtime.h>
#include <math.h>

#define BB   512
#define LL   512
#define VV   50000
#define EE   100
#define HH   100
#define GG   400
#define HIDN 50
#define KK   20
#define STARTK 18
#define ENDK   19
#define NEGV  (-1e6f)

// ---------------- scratch (device globals; no allocations allowed) ----------
__device__ float g_embproj[2][VV][GG];     // gate-interleaved, bias folded in
__device__ float g_h[2][BB][LL][HH];       // hf / hb (hb already un-reversed)
__device__ float g_probs[BB][LL][KK];

extern __shared__ float smem_dyn[];

__device__ __forceinline__ float sigf(float x) { return 1.0f / (1.0f + expf(-x)); }

// ---------------- K1: embproj[v][4q+m] = dot(emb[v], Wih[q+100m]) + b -------
__global__ void embproj_kernel(const float* __restrict__ emb,
                               const float* __restrict__ Wih_f, const float* __restrict__ b_f,
                               const float* __restrict__ Wih_b, const float* __restrict__ b_b)
{
    const int dir = blockIdx.y;
    const float* Wih  = dir ? Wih_b : Wih_f;
    const float* bias = dir ? b_b   : b_f;

    float* WihT  = smem_dyn;           // [100][400] gate-interleaved: [e][4q+m]
    float* bperm = WihT + 40000;       // [400]
    float* embs  = bperm + 400;        // [8][100]

    const int tid = threadIdx.x;
    for (int i = tid; i < 40000; i += 256) {
        int e = i / 400, g = i - e * 400;
        int q = g >> 2, m = g & 3;
        WihT[i] = Wih[(q + 100 * m) * EE + e];
    }
    for (int i = tid; i < 400; i += 256) {
        int q = i >> 2, m = i & 3;
        bperm[i] = bias[q + 100 * m];
    }

    const int vbase = blockIdx.x * 128;
    const int grp = tid / 100;
    const int q   = tid - grp * 100;
    const bool active = (tid < 200);

    for (int g0 = 0; g0 < 16; g0++) {
        const int vb = vbase + g0 * 8;
        __syncthreads();
        for (int i = tid; i < 800; i += 256) {
            int r = i / 100, e = i - r * 100;
            int v = vb + r;
            embs[i] = (v < VV) ? emb[(size_t)v * EE + e] : 0.0f;
        }
        __syncthreads();
        if (active) {
            float4 a[4];
            float4 binit = make_float4(bperm[4*q], bperm[4*q+1], bperm[4*q+2], bperm[4*q+3]);
            a[0] = binit; a[1] = binit; a[2] = binit; a[3] = binit;
            const float* er = &embs[grp * 400];
            #pragma unroll 4
            for (int e = 0; e < 100; e++) {
                float4 w = *reinterpret_cast<float4*>(&WihT[e * 400 + 4 * q]);
                float x0 = er[e], x1 = er[100 + e], x2 = er[200 + e], x3 = er[300 + e];
                a[0].x += w.x*x0; a[0].y += w.y*x0; a[0].z += w.z*x0; a[0].w += w.w*x0;
                a[1].x += w.x*x1; a[1].y += w.y*x1; a[1].z += w.z*x1; a[1].w += w.w*x1;
                a[2].x += w.x*x2; a[2].y += w.y*x2; a[2].z += w.z*x2; a[2].w += w.w*x2;
                a[3].x += w.x*x3; a[3].y += w.y*x3; a[3].z += w.z*x3; a[3].w += w.w*x3;
            }
            #pragma unroll
            for (int r = 0; r < 4; r++) {
                int v = vb + grp * 4 + r;
                if (v < VV)
                    *reinterpret_cast<float4*>(&g_embproj[dir][v][4 * q]) = a[r];
            }
        }
    }
}

// ---------------- K2: persistent BiLSTM recurrence --------------------------
// 128 blocks: blockIdx.y = dir, blockIdx.x = 8-row group. One wave on 148 SMs.
__global__ void lstm_kernel(const int* __restrict__ X, const int* __restrict__ lengths,
                            const float* __restrict__ Whh_f, const float* __restrict__ Whh_b,
                            const float* __restrict__ h0, const float* __restrict__ c0)
{
    const int dir = blockIdx.y;
    const int rowbase = blockIdx.x * 8;
    const float* Whh = dir ? Whh_b : Whh_f;

    float* WhhT = smem_dyn;                 // 40000 floats: [k][4q+m]
    float* h4s  = WhhT + 40000;             // [2][100][2] float4 = 1600 floats
    int*   toks = (int*)(h4s + 1600);       // [8][512]

    const int tid = threadIdx.x;
    for (int i = tid; i < 40000; i += 256) {
        int k = i / 400, g = i - k * 400;
        int q = g >> 2, m = g & 3;
        WhhT[i] = Whh[(q + 100 * m) * HH + k];
    }
    for (int i = tid; i < 8 * 512; i += 256) {
        int r = i >> 9, t = i & 511;
        int b = rowbase + r;
        int len = lengths[b];
        int idx = dir ? ((t < len) ? (len - 1 - t) : t) : t;
        toks[i] = X[b * LL + idx];
    }

    const int grp = tid / 100;
    const int q   = tid - grp * 100;
    const bool active = (tid < 200);

    float c[4]; int len4[4]; float* outp[4];
    if (active) {
        #pragma unroll
        for (int r = 0; r < 4; r++) {
            int b = rowbase + grp * 4 + r;
            len4[r] = lengths[b];
            c[r] = c0[(dir * BB + b) * HH + q];
            h4s[((0 * 100 + q) * 2 + grp) * 4 + r] = h0[(dir * BB + b) * HH + q];
            outp[r] = &g_h[dir][b][0][q];
        }
    }
    __syncthreads();

    const float* EP = &g_embproj[dir][0][0];
    float4 nxt[4];
    if (active) {
        #pragma unroll
        for (int r = 0; r < 4; r++) {
            int tok = toks[(grp * 4 + r) * 512];
            nxt[r] = *reinterpret_cast<const float4*>(EP + (size_t)tok * GG + 4 * q);
        }
    }

    int cur = 0;
    for (int t = 0; t < 512; t++) {
        if (active) {
            float4 a[4];
            a[0] = nxt[0]; a[1] = nxt[1]; a[2] = nxt[2]; a[3] = nxt[3];
            if (t < 511) {
                #pragma unroll
                for (int r = 0; r < 4; r++) {
                    int tok = toks[(grp * 4 + r) * 512 + t + 1];
                    nxt[r] = *reinterpret_cast<const float4*>(EP + (size_t)tok * GG + 4 * q);
                }
            }
            const float4* hb = reinterpret_cast<const float4*>(h4s) + cur * 200 + grp;
            const float* wp = WhhT + 4 * q;
            #pragma unroll 5
            for (int k = 0; k < 100; k++) {
                float4 w  = *reinterpret_cast<const float4*>(wp + k * 400);
                float4 hv = hb[k * 2];
                a[0].x += w.x*hv.x; a[0].y += w.y*hv.x; a[0].z += w.z*hv.x; a[0].w += w.w*hv.x;
                a[1].x += w.x*hv.y; a[1].y += w.y*hv.y; a[1].z += w.z*hv.y; a[1].w += w.w*hv.y;
                a[2].x += w.x*hv.z; a[2].y += w.y*hv.z; a[2].z += w.z*hv.z; a[2].w += w.w*hv.z;
                a[3].x += w.x*hv.w; a[3].y += w.y*hv.w; a[3].z += w.z*hv.w; a[3].w += w.w*hv.w;
            }
            const int nb = cur ^ 1;
            #pragma unroll
            for (int r = 0; r < 4; r++) {
                float ii = a[r].x, ff = a[r].y, gg = a[r].z, oo = a[r].w;
                float cn = sigf(ff) * c[r] + sigf(ii) * tanhf(gg);
                c[r] = cn;
                float hn = sigf(oo) * tanhf(cn);
                h4s[((nb * 100 + q) * 2 + grp) * 4 + r] = hn;
                int pos = dir ? ((t < len4[r]) ? (len4[r] - 1 - t) : t) : t;
                outp[r][pos * HH] = hn;
            }
        }
        __syncthreads();
        cur ^= 1;
    }
}

// ---------------- K3: masked concat + MLP -> probs --------------------------
__global__ void mlp_kernel(const int* __restrict__ lengths,
                           const float* __restrict__ W1, const float* __restrict__ b1,
                           const float* __restrict__ W2, const float* __restrict__ b2)
{
    float* W1s   = smem_dyn;        // [50][201]
    float* W2s   = W1s + 10050;     // [20][51]
    float* encs  = W2s + 1020;      // [32][201]
    float* hmids = encs + 6432;     // [32][51]
    float* b1s   = hmids + 1632;    // [50]
    float* b2s   = b1s + 50;        // [20]

    const int tid = threadIdx.x;
    for (int i = tid; i < 10000; i += 256) { int j = i / 200, k = i - j * 200; W1s[j * 201 + k] = W1[i]; }
    for (int i = tid; i < 1000;  i += 256) { int k2 = i / 50, j = i - k2 * 50;  W2s[k2 * 51 + j] = W2[i]; }
    if (tid < 50) b1s[tid] = b1[tid];
    if (tid < 20) b2s[tid] = b2[tid];

    const int n0 = blockIdx.x * 32;
    for (int i = tid; i < 32 * 200; i += 256) {
        int tk = i / 200, j = i - tk * 200;
        int n = n0 + tk, b = n >> 9, t = n & 511;
        float v = 0.0f;
        if (t < lengths[b]) v = (j < 100) ? g_h[0][b][t][j] : g_h[1][b][t][j - 100];
        encs[tk * 201 + j] = v;
    }
    __syncthreads();
    for (int o = tid; o < 1600; o += 256) {
        int tk = o / 50, j = o - tk * 50;
        float acc = b1s[j];
        const float* e = &encs[tk * 201];
        const float* w = &W1s[j * 201];
        #pragma unroll 4
        for (int k = 0; k < 200; k++) acc += e[k] * w[k];
        hmids[tk * 51 + j] = fmaxf(acc, 0.0f);
    }
    __syncthreads();
    for (int o = tid; o < 640; o += 256) {
        int tk = o / 20, k2 = o - tk * 20;
        float acc = b2s[k2];
        const float* hm = &hmids[tk * 51];
        const float* w  = &W2s[k2 * 51];
        #pragma unroll
        for (int j = 0; j < 50; j++) acc += hm[j] * w[j];
        int n = n0 + tk, b = n >> 9, t = n & 511;
        g_probs[b][t][k2] = acc;
    }
}

// ---------------- K4: Viterbi (one warp per batch row) ----------------------
__global__ void viterbi_kernel(const int* __restrict__ lengths,
                               const float* __restrict__ trans, float* __restrict__ out)
{
    __shared__ float trans_s[400];
    __shared__ signed char idx_s[512][20];
    __shared__ float path_s[512];

    const int tid = threadIdx.x;
    const int b = blockIdx.x;
    for (int i = tid; i < 400; i += 32) trans_s[i] = trans[i];
    __syncwarp();

    const int len = lengths[b];
    const int k2 = (tid < 20) ? tid : 19;
    float alpha = (tid == STARTK) ? 0.0f : NEGV;
    const float* pb = &g_probs[b][0][0];
    float pcur = pb[k2];

    for (int t = 0; t < len; t++) {
        float pnext = (t + 1 < len) ? pb[(t + 1) * 20 + k2] : 0.0f;
        float best = -3e38f; int arg = 0;
        #pragma unroll
        for (int k1 = 0; k1 < 20; k1++) {
            float av = __shfl_sync(0xffffffffu, alpha, k1);
            float v = (av + trans_s[k1 * 20 + k2]) + pcur;   // (alpha+trans)+p: JAX order
            if (v > best) { best = v; arg = k1; }            // strict > : first-index ties
        }
        if (tid < 20) { alpha = best; idx_s[t][tid] = (signed char)arg; }
        pcur = pnext;
    }

    float fin = alpha + trans_s[k2 * 20 + ENDK];
    float best = -3e38f; int arg = 0;
    #pragma unroll
    for (int k = 0; k < 20; k++) {
        float v = __shfl_sync(0xffffffffu, fin, k);
        if (v > best) { best = v; arg = k; }
    }

    if (tid == 0) {
        out[b] = best;
        int c = arg;
        for (int t = 511; t >= 0; t--) {
            if (t < len) { path_s[t] = (float)c; c = idx_s[t][c]; }
            else path_s[t] = -1.0f;
        }
    }
    __syncwarp();
    for (int t = tid; t < 512; t += 32) out[BB + (size_t)b * 512 + t] = path_s[t];
}

// ---------------- launch ----------------------------------------------------
extern "C" void kernel_launch(void* const* d_in, const int* in_sizes, int n_in,
                              void* d_out, int out_size)
{
    const int*   X       = (const int*)  d_in[0];
    const int*   lengths = (const int*)  d_in[1];
    const float* emb     = (const float*)d_in[2];
    const float* Wih_f   = (const float*)d_in[3];
    const float* Whh_f   = (const float*)d_in[4];
    const float* b_f     = (const float*)d_in[5];
    const float* Wih_b   = (const float*)d_in[6];
    const float* Whh_b   = (const float*)d_in[7];
    const float* b_b     = (const float*)d_in[8];
    const float* h0      = (const float*)d_in[9];
    const float* c0      = (const float*)d_in[10];
    const float* W1      = (const float*)d_in[11];
    const float* b1      = (const float*)d_in[12];
    const float* W2      = (const float*)d_in[13];
    const float* b2      = (const float*)d_in[14];
    const float* trans   = (const float*)d_in[15];
    float* out = (float*)d_out;

    const int EMB_SMEM  = (40000 + 400 + 800) * 4;                  // 164800
    const int LSTM_SMEM = (40000 + 1600) * 4 + 8 * 512 * 4;         // 182784
    const int MLP_SMEM  = (10050 + 1020 + 6432 + 1632 + 50 + 20) * 4; // 76816

    cudaFuncSetAttribute(embproj_kernel, cudaFuncAttributeMaxDynamicSharedMemorySize, EMB_SMEM);
    cudaFuncSetAttribute(lstm_kernel,    cudaFuncAttributeMaxDynamicSharedMemorySize, LSTM_SMEM);
    cudaFuncSetAttribute(mlp_kernel,     cudaFuncAttributeMaxDynamicSharedMemorySize, MLP_SMEM);

    embproj_kernel<<<dim3(391, 2, 1), 256, EMB_SMEM>>>(emb, Wih_f, b_f, Wih_b, b_b);
    lstm_kernel<<<dim3(64, 2, 1), 256, LSTM_SMEM>>>(X, lengths, Whh_f, Whh_b, h0, c0);
    mlp_kernel<<<8192, 256, MLP_SMEM>>>(lengths, W1, b1, W2, b2);
    viterbi_kernel<<<512, 32>>>(lengths, trans, out);
}

// round 2
// speedup vs baseline: 1.2551x; 1.2551x over previous
#include <cuda_runtime.h>
#include <math.h>

typedef unsigned long long u64;

#define BB   512
#define LL   512
#define VV   50000
#define EE   100
#define HH   100
#define GG   400
#define HIDN 50
#define KK   20
#define STARTK 18
#define ENDK   19
#define NEGV  (-1e6f)

// ---------------- scratch (device globals) ----------------------------------
__device__ float g_embproj[2][VV][GG];     // gate-interleaved [v][4q+m], bias folded
__device__ float g_h[2][BB][LL][HH];       // hf / hb (hb already un-reversed)
__device__ float g_probs[BB][LL][KK];

extern __shared__ float smem_dyn[];

__device__ __forceinline__ float sigf(float x) { return 1.0f / (1.0f + expf(-x)); }

__device__ __forceinline__ u64 fma2(u64 a, u64 b, u64 c) {
    u64 d; asm("fma.rn.f32x2 %0, %1, %2, %3;" : "=l"(d) : "l"(a), "l"(b), "l"(c)); return d;
}
__device__ __forceinline__ u64 pk2(float lo, float hi) {
    u64 r; asm("mov.b64 %0, {%1, %2};" : "=l"(r) : "f"(lo), "f"(hi)); return r;
}
__device__ __forceinline__ void up2(u64 v, float& lo, float& hi) {
    asm("mov.b64 {%0, %1}, %2;" : "=f"(lo), "=f"(hi) : "l"(v));
}

// ---------------- K1: embproj[v][4q+m] = dot(emb[v], Wih[q+100m]) + b -------
__global__ void embproj_kernel(const float* __restrict__ emb,
                               const float* __restrict__ Wih_f, const float* __restrict__ b_f,
                               const float* __restrict__ Wih_b, const float* __restrict__ b_b)
{
    const int dir = blockIdx.y;
    const float* Wih  = dir ? Wih_b : Wih_f;
    const float* bias = dir ? b_b   : b_f;

    float*  WihT  = smem_dyn;             // [100][400] gate-interleaved: [e][4q+m]
    float*  bperm = WihT + 40000;         // [400]
    float4* ed4   = (float4*)(bperm + 400); // dup-pairs: [(grp*100+e)*2+p] = (x,x,x',x')

    const int tid = threadIdx.x;
    for (int i = tid; i < 40000; i += 256) {
        int e = i / 400, g = i - e * 400;
        int q = g >> 2, m = g & 3;
        WihT[i] = Wih[(q + 100 * m) * EE + e];
    }
    for (int i = tid; i < 400; i += 256) {
        int q = i >> 2, m = i & 3;
        bperm[i] = bias[q + 100 * m];
    }

    const int vbase = blockIdx.x * 128;
    const int grp = tid / 100;
    const int q   = tid - grp * 100;
    const bool active = (tid < 200);

    for (int g0 = 0; g0 < 16; g0++) {
        const int vb = vbase + g0 * 8;
        __syncthreads();
        for (int i = tid; i < 400; i += 256) {
            int gi = i / 200, rem = i - gi * 200;
            int e = rem >> 1, p = rem & 1;
            int v0 = vb + gi * 4 + p * 2;
            float a0 = (v0 < VV)     ? emb[(size_t)v0 * EE + e]       : 0.0f;
            float a1 = (v0 + 1 < VV) ? emb[(size_t)(v0 + 1) * EE + e] : 0.0f;
            ed4[(gi * 100 + e) * 2 + p] = make_float4(a0, a0, a1, a1);
        }
        __syncthreads();
        if (active) {
            u64 bif = pk2(bperm[4*q], bperm[4*q+1]);
            u64 bgo = pk2(bperm[4*q+2], bperm[4*q+3]);
            u64 aif[4] = {bif, bif, bif, bif};
            u64 ago[4] = {bgo, bgo, bgo, bgo};
            const ulonglong2* wb = (const ulonglong2*)(WihT + 4 * q);  // stride 100/row
            const ulonglong2* xb = (const ulonglong2*)ed4 + grp * 200;
            #pragma unroll 4
            for (int e = 0; e < 100; e++) {
                ulonglong2 w2  = wb[e * 100];
                ulonglong2 x01 = xb[e * 2];
                ulonglong2 x23 = xb[e * 2 + 1];
                aif[0] = fma2(w2.x, x01.x, aif[0]); ago[0] = fma2(w2.y, x01.x, ago[0]);
                aif[1] = fma2(w2.x, x01.y, aif[1]); ago[1] = fma2(w2.y, x01.y, ago[1]);
                aif[2] = fma2(w2.x, x23.x, aif[2]); ago[2] = fma2(w2.y, x23.x, ago[2]);
                aif[3] = fma2(w2.x, x23.y, aif[3]); ago[3] = fma2(w2.y, x23.y, ago[3]);
            }
            #pragma unroll
            for (int r = 0; r < 4; r++) {
                int v = vb + grp * 4 + r;
                if (v < VV)
                    *reinterpret_cast<ulonglong2*>(&g_embproj[dir][v][4 * q]) =
                        make_ulonglong2(aif[r], ago[r]);
            }
        }
    }
}

// ---------------- K2: persistent BiLSTM recurrence (f32x2) ------------------
__global__ void lstm_kernel(const int* __restrict__ X, const int* __restrict__ lengths,
                            const float* __restrict__ Whh_f, const float* __restrict__ Whh_b,
                            const float* __restrict__ h0, const float* __restrict__ c0)
{
    const int dir = blockIdx.y;
    const int rowbase = blockIdx.x * 8;
    const float* Whh = dir ? Whh_b : Whh_f;

    float*  WhhT = smem_dyn;                 // 40000 floats: [k][4q+m]
    float4* hd4  = (float4*)(WhhT + 40000);  // dup h: idx = buf*400 + k*4 + grp*2 + p
    int*    toks = (int*)(hd4 + 800);        // [8][512]

    const int tid = threadIdx.x;
    for (int i = tid; i < 40000; i += 256) {
        int k = i / 400, g = i - k * 400;
        int q = g >> 2, m = g & 3;
        WhhT[i] = Whh[(q + 100 * m) * HH + k];
    }
    for (int i = tid; i < 8 * 512; i += 256) {
        int r = i >> 9, t = i & 511;
        int b = rowbase + r;
        int len = lengths[b];
        int idx = dir ? ((t < len) ? (len - 1 - t) : t) : t;
        toks[i] = X[b * LL + idx];
    }

    const int grp = tid / 100;
    const int q   = tid - grp * 100;
    const bool active = (tid < 200);

    float c[4]; int len4[4]; float* outp[4];
    if (active) {
        float hi[4];
        #pragma unroll
        for (int r = 0; r < 4; r++) {
            int b = rowbase + grp * 4 + r;
            len4[r] = lengths[b];
            c[r]  = c0[(dir * BB + b) * HH + q];
            hi[r] = h0[(dir * BB + b) * HH + q];
            outp[r] = &g_h[dir][b][0][q];
        }
        hd4[q * 4 + grp * 2 + 0] = make_float4(hi[0], hi[0], hi[1], hi[1]);
        hd4[q * 4 + grp * 2 + 1] = make_float4(hi[2], hi[2], hi[3], hi[3]);
    }
    __syncthreads();

    const float* EP = &g_embproj[dir][0][0];
    ulonglong2 nx[4];
    if (active) {
        #pragma unroll
        for (int r = 0; r < 4; r++) {
            int tok = toks[(grp * 4 + r) * 512];
            nx[r] = *reinterpret_cast<const ulonglong2*>(EP + (size_t)tok * GG + 4 * q);
        }
    }

    int cur = 0;
    for (int t = 0; t < 512; t++) {
        if (active) {
            u64 aif[4], ago[4];
            #pragma unroll
            for (int r = 0; r < 4; r++) { aif[r] = nx[r].x; ago[r] = nx[r].y; }
            if (t < 511) {
                #pragma unroll
                for (int r = 0; r < 4; r++) {
                    int tok = toks[(grp * 4 + r) * 512 + t + 1];
                    nx[r] = *reinterpret_cast<const ulonglong2*>(EP + (size_t)tok * GG + 4 * q);
                }
            }
            const ulonglong2* wb = (const ulonglong2*)(WhhT + 4 * q);        // stride 100/row
            const ulonglong2* hb = (const ulonglong2*)hd4 + cur * 400 + grp * 2;
            #pragma unroll 5
            for (int k = 0; k < 100; k++) {
                ulonglong2 w2 = wb[k * 100];
                ulonglong2 hA = hb[k * 4];       // (h0,h0),(h1,h1)
                ulonglong2 hB = hb[k * 4 + 1];   // (h2,h2),(h3,h3)
                aif[0] = fma2(w2.x, hA.x, aif[0]); ago[0] = fma2(w2.y, hA.x, ago[0]);
                aif[1] = fma2(w2.x, hA.y, aif[1]); ago[1] = fma2(w2.y, hA.y, ago[1]);
                aif[2] = fma2(w2.x, hB.x, aif[2]); ago[2] = fma2(w2.y, hB.x, ago[2]);
                aif[3] = fma2(w2.x, hB.y, aif[3]); ago[3] = fma2(w2.y, hB.y, ago[3]);
            }
            const int nb = cur ^ 1;
            float hn[4];
            #pragma unroll
            for (int r = 0; r < 4; r++) {
                float ii, ff, gg, oo;
                up2(aif[r], ii, ff);
                up2(ago[r], gg, oo);
                float cn = sigf(ff) * c[r] + sigf(ii) * tanhf(gg);
                c[r] = cn;
                float hv = sigf(oo) * tanhf(cn);
                hn[r] = hv;
                int pos = dir ? ((t < len4[r]) ? (len4[r] - 1 - t) : t) : t;
                outp[r][pos * HH] = hv;
            }
            hd4[nb * 400 + q * 4 + grp * 2 + 0] = make_float4(hn[0], hn[0], hn[1], hn[1]);
            hd4[nb * 400 + q * 4 + grp * 2 + 1] = make_float4(hn[2], hn[2], hn[3], hn[3]);
        }
        __syncthreads();
        cur ^= 1;
    }
}

// ---------------- K3: MLP, 1 token/thread, f32x2, fused stage2 --------------
__global__ void mlp_kernel(const int* __restrict__ lengths,
                           const float* __restrict__ W1, const float* __restrict__ b1,
                           const float* __restrict__ W2, const float* __restrict__ b2)
{
    float* W1Ts = smem_dyn;          // [200][52], pad j 50->52 with zeros
    float* W2Ts = W1Ts + 10400;      // [50][20]
    float* b1s  = W2Ts + 1000;       // [52]
    float* b2s  = b1s + 52;          // [20]

    const int tid = threadIdx.x;
    for (int i = tid; i < 10400; i += 256) {
        int k = i / 52, j = i - k * 52;
        W1Ts[i] = (j < 50) ? W1[j * 200 + k] : 0.0f;
    }
    for (int i = tid; i < 1000; i += 256) {
        int j = i / 20, k2 = i - j * 20;
        W2Ts[i] = W2[k2 * 50 + j];
    }
    if (tid < 52) b1s[tid] = (tid < 50) ? b1[tid] : 0.0f;
    if (tid < 20) b2s[tid] = b2[tid];
    __syncthreads();

    const int n = blockIdx.x * 256 + tid;
    const int b = n >> 9, t = n & 511;
    if (t >= lengths[b]) return;   // probs at t>=len never read by viterbi

    u64 acc[26];
    #pragma unroll
    for (int p = 0; p < 26; p++) acc[p] = pk2(b1s[2 * p], b1s[2 * p + 1]);

    #pragma unroll
    for (int half = 0; half < 2; half++) {
        const float4* g = (const float4*)&g_h[half][b][t][0];
        #pragma unroll 2
        for (int cchunk = 0; cchunk < 25; cchunk++) {
            float4 ex = g[cchunk];
            #pragma unroll
            for (int u = 0; u < 4; u++) {
                int k = half * 100 + cchunk * 4 + u;
                float x = (u == 0) ? ex.x : (u == 1) ? ex.y : (u == 2) ? ex.z : ex.w;
                u64 xd = pk2(x, x);
                const ulonglong2* wr = (const ulonglong2*)&W1Ts[k * 52];
                #pragma unroll
                for (int p = 0; p < 13; p++) {
                    ulonglong2 wv = wr[p];
                    acc[2 * p]     = fma2(wv.x, xd, acc[2 * p]);
                    acc[2 * p + 1] = fma2(wv.y, xd, acc[2 * p + 1]);
                }
            }
        }
    }

    u64 a2[10];
    #pragma unroll
    for (int p = 0; p < 10; p++) a2[p] = pk2(b2s[2 * p], b2s[2 * p + 1]);

    #pragma unroll
    for (int p = 0; p < 25; p++) {          // 50 hmid values = 25 pairs
        float ha, hb2;
        up2(acc[p], ha, hb2);
        ha  = fmaxf(ha, 0.0f);
        hb2 = fmaxf(hb2, 0.0f);
        u64 hd0 = pk2(ha, ha), hd1 = pk2(hb2, hb2);
        const ulonglong2* w0 = (const ulonglong2*)&W2Ts[(2 * p) * 20];
        const ulonglong2* w1 = (const ulonglong2*)&W2Ts[(2 * p + 1) * 20];
        #pragma unroll
        for (int pp = 0; pp < 5; pp++) {
            ulonglong2 wv0 = w0[pp];
            a2[2 * pp]     = fma2(wv0.x, hd0, a2[2 * pp]);
            a2[2 * pp + 1] = fma2(wv0.y, hd0, a2[2 * pp + 1]);
        }
        #pragma unroll
        for (int pp = 0; pp < 5; pp++) {
            ulonglong2 wv1 = w1[pp];
            a2[2 * pp]     = fma2(wv1.x, hd1, a2[2 * pp]);
            a2[2 * pp + 1] = fma2(wv1.y, hd1, a2[2 * pp + 1]);
        }
    }

    float o[20];
    #pragma unroll
    for (int p = 0; p < 10; p++) up2(a2[p], o[2 * p], o[2 * p + 1]);
    float4* op = (float4*)&g_probs[b][t][0];
    #pragma unroll
    for (int p = 0; p < 5; p++)
        op[p] = make_float4(o[4 * p], o[4 * p + 1], o[4 * p + 2], o[4 * p + 3]);
}

// ---------------- K4: Viterbi (1 warp/row, smem probs, reg trans) -----------
__global__ void __launch_bounds__(32) viterbi_kernel(const int* __restrict__ lengths,
                               const float* __restrict__ trans, float* __restrict__ out)
{
    float*       ps     = smem_dyn;                        // [512*20]
    signed char* bp     = (signed char*)(smem_dyn + 10240); // [512*20]
    float*       path_s = (float*)(bp + 10240);            // [512]

    const int tid = threadIdx.x;
    const int b = blockIdx.x;

    const float4* pin = (const float4*)&g_probs[b][0][0];
    float4* pss = (float4*)ps;
    for (int i = tid; i < 2560; i += 32) pss[i] = pin[i];

    const int k2 = (tid < 20) ? tid : 19;
    float tr[20];
    #pragma unroll
    for (int k1 = 0; k1 < 20; k1++) tr[k1] = trans[k1 * 20 + k2];
    const float trE = trans[k2 * 20 + ENDK];
    const int len = lengths[b];

    float alpha = (tid == STARTK) ? 0.0f : NEGV;
    __syncwarp();
    float pcur = ps[k2];

    for (int t = 0; t < len; t++) {
        float pnext = (t + 1 < len) ? ps[(t + 1) * 20 + k2] : 0.0f;
        float vv[20];
        #pragma unroll
        for (int k1 = 0; k1 < 20; k1++)
            vv[k1] = (__shfl_sync(0xffffffffu, alpha, k1) + tr[k1]) + pcur; // JAX assoc order

        // 4 chains of 5, left-priority combine => first-index-of-max (strict >)
        float v0 = vv[0]; int i0 = 0;
        #pragma unroll
        for (int i = 1; i < 5; i++)  if (vv[i] > v0) { v0 = vv[i]; i0 = i; }
        float v1 = vv[5]; int i1 = 5;
        #pragma unroll
        for (int i = 6; i < 10; i++) if (vv[i] > v1) { v1 = vv[i]; i1 = i; }
        float v2 = vv[10]; int i2 = 10;
        #pragma unroll
        for (int i = 11; i < 15; i++) if (vv[i] > v2) { v2 = vv[i]; i2 = i; }
        float v3 = vv[15]; int i3 = 15;
        #pragma unroll
        for (int i = 16; i < 20; i++) if (vv[i] > v3) { v3 = vv[i]; i3 = i; }
        if (v1 > v0) { v0 = v1; i0 = i1; }
        if (v3 > v2) { v2 = v3; i2 = i3; }
        if (v2 > v0) { v0 = v2; i0 = i2; }

        if (tid < 20) bp[t * 20 + tid] = (signed char)i0;
        alpha = v0;
        pcur = pnext;
    }

    float fin = alpha + trE;
    float fv[20];
    #pragma unroll
    for (int k = 0; k < 20; k++) fv[k] = __shfl_sync(0xffffffffu, fin, k);
    float v0 = fv[0]; int i0 = 0;
    #pragma unroll
    for (int i = 1; i < 20; i++) if (fv[i] > v0) { v0 = fv[i]; i0 = i; }

    if (tid == 0) {
        out[b] = v0;
        int c = i0;
        for (int t = 511; t >= 0; t--) {
            if (t < len) { path_s[t] = (float)c; c = bp[t * 20 + c]; }
            else path_s[t] = -1.0f;
        }
    }
    __syncwarp();
    for (int t = tid; t < 512; t += 32) out[BB + (size_t)b * 512 + t] = path_s[t];
}

// ---------------- launch ----------------------------------------------------
extern "C" void kernel_launch(void* const* d_in, const int* in_sizes, int n_in,
                              void* d_out, int out_size)
{
    const int*   X       = (const int*)  d_in[0];
    const int*   lengths = (const int*)  d_in[1];
    const float* emb     = (const float*)d_in[2];
    const float* Wih_f   = (const float*)d_in[3];
    const float* Whh_f   = (const float*)d_in[4];
    const float* b_f     = (const float*)d_in[5];
    const float* Wih_b   = (const float*)d_in[6];
    const float* Whh_b   = (const float*)d_in[7];
    const float* b_b     = (const float*)d_in[8];
    const float* h0      = (const float*)d_in[9];
    const float* c0      = (const float*)d_in[10];
    const float* W1      = (const float*)d_in[11];
    const float* b1      = (const float*)d_in[12];
    const float* W2      = (const float*)d_in[13];
    const float* b2      = (const float*)d_in[14];
    const float* trans   = (const float*)d_in[15];
    float* out = (float*)d_out;

    const int EMB_SMEM  = (40000 + 400 + 1600) * 4;          // 168000
    const int LSTM_SMEM = 40000 * 4 + 800 * 16 + 8*512*4;    // 189184
    const int MLP_SMEM  = (10400 + 1000 + 52 + 20) * 4;      // 45888
    const int VIT_SMEM  = 10240 * 4 + 10240 + 512 * 4;       // 53248

    cudaFuncSetAttribute(embproj_kernel, cudaFuncAttributeMaxDynamicSharedMemorySize, EMB_SMEM);
    cudaFuncSetAttribute(lstm_kernel,    cudaFuncAttributeMaxDynamicSharedMemorySize, LSTM_SMEM);
    cudaFuncSetAttribute(mlp_kernel,     cudaFuncAttributeMaxDynamicSharedMemorySize, MLP_SMEM);
    cudaFuncSetAttribute(viterbi_kernel, cudaFuncAttributeMaxDynamicSharedMemorySize, VIT_SMEM);

    embproj_kernel<<<dim3(391, 2, 1), 256, EMB_SMEM>>>(emb, Wih_f, b_f, Wih_b, b_b);
    lstm_kernel<<<dim3(64, 2, 1), 256, LSTM_SMEM>>>(X, lengths, Whh_f, Whh_b, h0, c0);
    mlp_kernel<<<1024, 256, MLP_SMEM>>>(lengths, W1, b1, W2, b2);
    viterbi_kernel<<<512, 32, VIT_SMEM>>>(lengths, trans, out);
}